// round 10
// baseline (speedup 1.0000x reference)
#include <cuda_runtime.h>
#include <cuda_bf16.h>
#include <cstdint>

// Problem constants
#define Nn 100000
#define Ee 600000
#define D  128
#define NB_SCAN 391
#define MT 64                    // gemm tile rows (nodes)
#define NTILES 1563              // ceil(Nn/64)
#define THREADS_G 256

// smem byte offsets for k_gemm (row pitch 528 B = 264 bf16 / 132 f32)
#define PITCH 528
#define SB_WHI  0                // 128 rows * 528 = 67584
#define SB_WLO  67584
#define SB_AHI  135168           // 64 rows * 528 = 33792 (reused as C f32)
#define SB_ALO  168960
#define SB_BIAS 202752
#define SB_BNS  203264
#define SB_BNT  203776
#define SB_FCW  204288
#define SMEM_G  204544

// gap-padded C layout: word index for (row, col), conflict-free phases
#define CIDX(r, c) ((r) * 132 + (c) + ((c) >> 5))

typedef unsigned short ushort_t;
typedef unsigned int uint_t;

// ---------------- device scratch ------------------------------------------
__device__ int   g_deg[Nn];
__device__ int   g_off[Nn];
__device__ int   g_cur[Nn];
__device__ int   g_elist[Ee];
__device__ int   g_bsum[512];
__device__ __align__(16) float g_h[(size_t)Nn * D];
__device__ __align__(16) float g_mean[(size_t)Nn * D];
__device__ __align__(16) float g_bnsum[D];
__device__ __align__(16) float g_bnsq[D];
__device__ __align__(16) float g_bns[D];
__device__ __align__(16) float g_bnt[D];
__device__ float g_preds_fb[Nn];
__device__ __align__(16) float g_embed_fb[(size_t)Nn * D];

__device__ __forceinline__ void split_bf16(float v, ushort_t& h, ushort_t& l) {
    __nv_bfloat16 bh = __float2bfloat16(v);
    float r = v - __bfloat162float(bh);
    __nv_bfloat16 blo = __float2bfloat16(r);
    h = __bfloat16_as_ushort(bh);
    l = __bfloat16_as_ushort(blo);
}

// ---------------- CSR build ------------------------------------------------
__global__ void k_zero() {
    int i = blockIdx.x * blockDim.x + threadIdx.x;
    if (i < Nn) g_deg[i] = 0;
    if (i < D) { g_bnsum[i] = 0.f; g_bnsq[i] = 0.f; }
}
__global__ void k_degree(const int* __restrict__ dst) {
    int e = blockIdx.x * blockDim.x + threadIdx.x;
    if (e < Ee) atomicAdd(&g_deg[dst[e]], 1);
}
__global__ void k_scan1() {
    __shared__ int s[256];
    int i = blockIdx.x * 256 + threadIdx.x;
    int v = (i < Nn) ? g_deg[i] : 0;
    s[threadIdx.x] = v; __syncthreads();
    for (int d = 128; d > 0; d >>= 1) {
        if (threadIdx.x < d) s[threadIdx.x] += s[threadIdx.x + d];
        __syncthreads();
    }
    if (threadIdx.x == 0) g_bsum[blockIdx.x] = s[0];
}
__global__ void k_scan2() {
    __shared__ int s[512];
    int t = threadIdx.x;
    int v = (t < NB_SCAN) ? g_bsum[t] : 0;
    s[t] = v; __syncthreads();
    for (int d = 1; d < 512; d <<= 1) {
        int x = (t >= d) ? s[t - d] : 0;
        __syncthreads(); s[t] += x; __syncthreads();
    }
    if (t < NB_SCAN) g_bsum[t] = s[t] - v;
}
__global__ void k_scan3() {
    __shared__ int s[256];
    int t = threadIdx.x;
    int i = blockIdx.x * 256 + t;
    int v = (i < Nn) ? g_deg[i] : 0;
    s[t] = v; __syncthreads();
    for (int d = 1; d < 256; d <<= 1) {
        int x = (t >= d) ? s[t - d] : 0;
        __syncthreads(); s[t] += x; __syncthreads();
    }
    if (i < Nn) {
        int off = g_bsum[blockIdx.x] + s[t] - v;
        g_off[i] = off; g_cur[i] = off;
    }
}
__global__ void k_fill(const int* __restrict__ src, const int* __restrict__ dst) {
    int e = blockIdx.x * blockDim.x + threadIdx.x;
    if (e < Ee) {
        int p = atomicAdd(&g_cur[dst[e]], 1);
        g_elist[p] = src[e];
    }
}

// ---------------- mean aggregation (warp per node) -------------------------
__global__ __launch_bounds__(256)
void k_agg(const float* __restrict__ xin) {
    int w = (blockIdx.x * blockDim.x + threadIdx.x) >> 5;
    int lane = threadIdx.x & 31;
    if (w >= Nn) return;
    int off = g_off[w], dg = g_deg[w];
    const float4* xi4 = (const float4*)xin;
    float4 a0 = make_float4(0, 0, 0, 0), a1 = make_float4(0, 0, 0, 0);
    int e = 0;
    for (; e + 1 < dg; e += 2) {
        int s0 = __ldg(&g_elist[off + e]);
        int s1 = __ldg(&g_elist[off + e + 1]);
        float4 v0 = __ldg(&xi4[(size_t)s0 * 32 + lane]);
        float4 v1 = __ldg(&xi4[(size_t)s1 * 32 + lane]);
        a0.x += v0.x; a0.y += v0.y; a0.z += v0.z; a0.w += v0.w;
        a1.x += v1.x; a1.y += v1.y; a1.z += v1.z; a1.w += v1.w;
    }
    if (e < dg) {
        int s0 = __ldg(&g_elist[off + e]);
        float4 v0 = __ldg(&xi4[(size_t)s0 * 32 + lane]);
        a0.x += v0.x; a0.y += v0.y; a0.z += v0.z; a0.w += v0.w;
    }
    float inv = 1.f / (float)max(dg, 1);
    float4 m = make_float4((a0.x + a1.x) * inv, (a0.y + a1.y) * inv,
                           (a0.z + a1.z) * inv, (a0.w + a1.w) * inv);
    ((float4*)g_mean)[(size_t)w * 32 + lane] = m;
}

// ---------------- BN stats over g_h ----------------------------------------
__global__ __launch_bounds__(256)
void k_bnstats() {
    __shared__ float sh[256], shq[256];
    int col = threadIdx.x & 127;
    int rg  = threadIdx.x >> 7;
    size_t r0 = (size_t)blockIdx.x * 1024 + rg;
    float s = 0.f, q = 0.f;
    for (int i = 0; i < 512; i++) {
        size_t r = r0 + 2 * (size_t)i;
        if (r < Nn) {
            float v = g_h[r * D + col];
            s += v; q += v * v;
        }
    }
    sh[threadIdx.x] = s; shq[threadIdx.x] = q;
    __syncthreads();
    if (threadIdx.x < 128) {
        atomicAdd(&g_bnsum[col], sh[threadIdx.x] + sh[threadIdx.x + 128]);
        atomicAdd(&g_bnsq[col],  shq[threadIdx.x] + shq[threadIdx.x + 128]);
    }
}
__global__ void k_bnfin(const float* __restrict__ gamma,
                        const float* __restrict__ beta) {
    int j = threadIdx.x;
    if (j < D) {
        float mu  = g_bnsum[j] / (float)Nn;
        float var = g_bnsq[j] / (float)Nn - mu * mu;
        float s   = gamma[j] * rsqrtf(var + 1e-5f);
        g_bns[j] = s;
        g_bnt[j] = beta[j] - mu * s;
    }
}

// ---------------- mma.sync bf16 3-term-split GEMM + epilogue ---------------
__global__ __launch_bounds__(THREADS_G, 1)
void k_gemm(const float* __restrict__ xin,
            const float* __restrict__ Wl, const float* __restrict__ Wr,
            const float* __restrict__ bl,
            float* __restrict__ hout, float* __restrict__ preds,
            const float* __restrict__ fcw, const float* __restrict__ fcb,
            int layer) {
    extern __shared__ char smg[];
    int tid = threadIdx.x;
    int warp = tid >> 5, lane = tid & 31;
    int g = lane >> 2, tg = lane & 3;
    int mw = warp & 1, nw = warp >> 1;

    float* sBias = (float*)(smg + SB_BIAS);
    float* sBns  = (float*)(smg + SB_BNS);
    float* sBnt  = (float*)(smg + SB_BNT);
    float* sFcw  = (float*)(smg + SB_FCW);

    // ---- stage W transposed + split: lane = n (coalesced LDG), STS.64 ------
    {
        int n = (warp & 3) * 32 + lane;          // 4 warps cover n, 2 k-halves
        int kh = warp >> 2;                       // 0: Wl, 1: Wr
        const float* Wsrc = (kh == 0) ? Wl : Wr;
        #pragma unroll 4
        for (int kq = 0; kq < 32; kq++) {
            int k0 = kq * 4;                      // local k within half
            float v0 = __ldg(&Wsrc[(size_t)(k0 + 0) * D + n]);
            float v1 = __ldg(&Wsrc[(size_t)(k0 + 1) * D + n]);
            float v2 = __ldg(&Wsrc[(size_t)(k0 + 2) * D + n]);
            float v3 = __ldg(&Wsrc[(size_t)(k0 + 3) * D + n]);
            ushort_t h0, l0, h1, l1, h2, l2, h3, l3;
            split_bf16(v0, h0, l0); split_bf16(v1, h1, l1);
            split_bf16(v2, h2, l2); split_bf16(v3, h3, l3);
            uint2 hv = make_uint2((uint_t)h0 | ((uint_t)h1 << 16),
                                  (uint_t)h2 | ((uint_t)h3 << 16));
            uint2 lv = make_uint2((uint_t)l0 | ((uint_t)l1 << 16),
                                  (uint_t)l2 | ((uint_t)l3 << 16));
            int kg = kh * 128 + k0;               // global stacked k
            *(uint2*)(smg + SB_WHI + n * PITCH + kg * 2) = hv;
            *(uint2*)(smg + SB_WLO + n * PITCH + kg * 2) = lv;
        }
    }
    if (tid < 128) {
        sBias[tid] = bl[tid];
        if (layer == 2) { sBns[tid] = g_bns[tid]; sBnt[tid] = g_bnt[tid]; }
    }
    if (layer == 2 && tid < 64) sFcw[tid] = fcw[tid];
    __syncthreads();
    float fcb0 = (layer == 2) ? __ldg(fcb) : 0.f;

    float4 bnsV = make_float4(0, 0, 0, 0), bntV = make_float4(0, 0, 0, 0);
    if (layer == 2) {
        bnsV = ((const float4*)sBns)[lane];
        bntV = ((const float4*)sBnt)[lane];
    }

    int er = tid >> 2, part = tid & 3;            // epilogue row / quarter
    float* sC = (float*)(smg + SB_AHI);

    for (int tile = blockIdx.x; tile < NTILES; tile += gridDim.x) {
        int base = tile * MT;

        // ---- stage A: warp = 8 rows, lane = 4 consecutive cols (coalesced) -
        #pragma unroll
        for (int r = 0; r < 8; r++) {
            int row = warp * 8 + r;
            int node = base + row;
            bool valid = node < Nn;
            int dg = 1;
            if (layer == 2 && valid) dg = g_deg[node];
            #pragma unroll
            for (int h = 0; h < 2; h++) {
                float4 f = make_float4(0, 0, 0, 0);
                if (valid && !(layer == 2 && h == 0 && dg == 0)) {
                    const float4* p = (h == 0)
                        ? (const float4*)(g_mean + (size_t)node * D)
                        : (const float4*)(xin + (size_t)node * D);
                    f = __ldg(p + lane);
                    if (layer == 2) {
                        f.x = f.x * bnsV.x + bntV.x;
                        f.y = f.y * bnsV.y + bntV.y;
                        f.z = f.z * bnsV.z + bntV.z;
                        f.w = f.w * bnsV.w + bntV.w;
                    }
                }
                ushort_t h0, l0, h1, l1, h2, l2, h3, l3;
                split_bf16(f.x, h0, l0); split_bf16(f.y, h1, l1);
                split_bf16(f.z, h2, l2); split_bf16(f.w, h3, l3);
                uint2 hv = make_uint2((uint_t)h0 | ((uint_t)h1 << 16),
                                      (uint_t)h2 | ((uint_t)h3 << 16));
                uint2 lv = make_uint2((uint_t)l0 | ((uint_t)l1 << 16),
                                      (uint_t)l2 | ((uint_t)l3 << 16));
                int ob = row * PITCH + h * 256 + lane * 8;
                *(uint2*)(smg + SB_AHI + ob) = hv;
                *(uint2*)(smg + SB_ALO + ob) = lv;
            }
        }
        __syncthreads();

        // ---- mma: frag-reuse, 3 split terms from registers ----------------
        float acc[2][4][4];
        #pragma unroll
        for (int mi = 0; mi < 2; mi++)
            #pragma unroll
            for (int ni = 0; ni < 4; ni++)
                #pragma unroll
                for (int j = 0; j < 4; j++) acc[mi][ni][j] = 0.f;

        #pragma unroll 2
        for (int ks = 0; ks < 16; ks++) {
            int kb = ks * 32 + tg * 4;
            uint_t ah[2][4], al[2][4], bh[4][2], blo[4][2];
            #pragma unroll
            for (int mi = 0; mi < 2; mi++) {
                const char* p = smg + SB_AHI + (mw * 32 + mi * 16 + g) * PITCH + kb;
                ah[mi][0] = *(const uint_t*)p;
                ah[mi][1] = *(const uint_t*)(p + 8 * PITCH);
                ah[mi][2] = *(const uint_t*)(p + 16);
                ah[mi][3] = *(const uint_t*)(p + 8 * PITCH + 16);
                const char* q = smg + SB_ALO + (mw * 32 + mi * 16 + g) * PITCH + kb;
                al[mi][0] = *(const uint_t*)q;
                al[mi][1] = *(const uint_t*)(q + 8 * PITCH);
                al[mi][2] = *(const uint_t*)(q + 16);
                al[mi][3] = *(const uint_t*)(q + 8 * PITCH + 16);
            }
            #pragma unroll
            for (int ni = 0; ni < 4; ni++) {
                const char* p = smg + SB_WHI + (nw * 32 + ni * 8 + g) * PITCH + kb;
                bh[ni][0] = *(const uint_t*)p;
                bh[ni][1] = *(const uint_t*)(p + 16);
                const char* q = smg + SB_WLO + (nw * 32 + ni * 8 + g) * PITCH + kb;
                blo[ni][0] = *(const uint_t*)q;
                blo[ni][1] = *(const uint_t*)(q + 16);
            }
            #pragma unroll
            for (int ni = 0; ni < 4; ni++) {
                #pragma unroll
                for (int mi = 0; mi < 2; mi++) {
                    asm volatile(
                        "mma.sync.aligned.m16n8k16.row.col.f32.bf16.bf16.f32 "
                        "{%0,%1,%2,%3}, {%4,%5,%6,%7}, {%8,%9}, {%0,%1,%2,%3};"
                        : "+f"(acc[mi][ni][0]), "+f"(acc[mi][ni][1]),
                          "+f"(acc[mi][ni][2]), "+f"(acc[mi][ni][3])
                        : "r"(ah[mi][0]), "r"(ah[mi][1]), "r"(ah[mi][2]), "r"(ah[mi][3]),
                          "r"(bh[ni][0]), "r"(bh[ni][1]));
                    asm volatile(
                        "mma.sync.aligned.m16n8k16.row.col.f32.bf16.bf16.f32 "
                        "{%0,%1,%2,%3}, {%4,%5,%6,%7}, {%8,%9}, {%0,%1,%2,%3};"
                        : "+f"(acc[mi][ni][0]), "+f"(acc[mi][ni][1]),
                          "+f"(acc[mi][ni][2]), "+f"(acc[mi][ni][3])
                        : "r"(ah[mi][0]), "r"(ah[mi][1]), "r"(ah[mi][2]), "r"(ah[mi][3]),
                          "r"(blo[ni][0]), "r"(blo[ni][1]));
                    asm volatile(
                        "mma.sync.aligned.m16n8k16.row.col.f32.bf16.bf16.f32 "
                        "{%0,%1,%2,%3}, {%4,%5,%6,%7}, {%8,%9}, {%0,%1,%2,%3};"
                        : "+f"(acc[mi][ni][0]), "+f"(acc[mi][ni][1]),
                          "+f"(acc[mi][ni][2]), "+f"(acc[mi][ni][3])
                        : "r"(al[mi][0]), "r"(al[mi][1]), "r"(al[mi][2]), "r"(al[mi][3]),
                          "r"(bh[ni][0]), "r"(bh[ni][1]));
                }
            }
        }
        __syncthreads();   // all A reads done before C overwrites SB_AHI

        // ---- write C frags to gap-padded smem -----------------------------
        #pragma unroll
        for (int mi = 0; mi < 2; mi++) {
            #pragma unroll
            for (int ni = 0; ni < 4; ni++) {
                int row = mw * 32 + mi * 16 + g;
                int col = nw * 32 + ni * 8 + tg * 2;
                int w0 = CIDX(row, col);
                sC[w0]     = acc[mi][ni][0];
                sC[w0 + 1] = acc[mi][ni][1];
                int w1 = CIDX(row + 8, col);
                sC[w1]     = acc[mi][ni][2];
                sC[w1 + 1] = acc[mi][ni][3];
            }
        }
        __syncthreads();

        // ---- phase A: 4 threads/row: bias + L2 norm (+relu / preds) -------
        {
            int node = base + er;
            float o[32];
            float ss = 0.f;
            #pragma unroll
            for (int i = 0; i < 32; i++) {
                int c = part * 32 + i;
                float v = sC[CIDX(er, c)] + sBias[c];
                o[i] = v; ss += v * v;
            }
            ss += __shfl_xor_sync(0xffffffffu, ss, 1);
            ss += __shfl_xor_sync(0xffffffffu, ss, 2);
            float inv = 1.f / fmaxf(sqrtf(ss), 1e-12f);
            if (layer == 1) {
                #pragma unroll
                for (int i = 0; i < 32; i++) o[i] = fmaxf(o[i] * inv, 0.f);
            } else {
                #pragma unroll
                for (int i = 0; i < 32; i++) o[i] *= inv;
            }
            #pragma unroll
            for (int i = 0; i < 32; i++)
                sC[CIDX(er, part * 32 + i)] = o[i];
            if (layer == 2 && node < Nn) {
                float p = 0.f;
                if (part < 2) {
                    #pragma unroll
                    for (int i = 0; i < 32; i++)
                        p += o[i] * sFcw[part * 32 + i];
                }
                p += __shfl_xor_sync(0xffffffffu, p, 1);
                if (part == 0) preds[node] = p + fcb0;
            }
        }
        __syncthreads();

        // ---- phase B: coalesced copy-out, warp = 8 rows -------------------
        #pragma unroll
        for (int r = 0; r < 8; r++) {
            int row = warp * 8 + r;
            int node = base + row;
            if (node < Nn) {
                int wbase = row * 132 + 4 * lane + (lane >> 3);
                float4 v;
                v.x = sC[wbase];
                v.y = sC[wbase + 1];
                v.z = sC[wbase + 2];
                v.w = sC[wbase + 3];
                *(float4*)(hout + (size_t)node * D + 4 * lane) = v;
            }
        }
        __syncthreads();   // sC free before next tile's A staging
    }
}

// ---------------- launch ----------------------------------------------------
extern "C" void kernel_launch(void* const* d_in, const int* in_sizes, int n_in,
                              void* d_out, int out_size) {
    const float* x     = (const float*)d_in[0];
    const int*   ei    = (const int*)d_in[1];
    const int*   src   = ei;
    const int*   dst   = ei + Ee;
    const float* W1l   = (const float*)d_in[2];
    const float* b1l   = (const float*)d_in[3];
    const float* W1r   = (const float*)d_in[4];
    const float* gamma = (const float*)d_in[5];
    const float* beta  = (const float*)d_in[6];
    const float* W2l   = (const float*)d_in[7];
    const float* b2l   = (const float*)d_in[8];
    const float* W2r   = (const float*)d_in[9];
    const float* fcw   = (const float*)d_in[10];
    const float* fcb   = (const float*)d_in[11];

    float* ph = nullptr;
    cudaGetSymbolAddress((void**)&ph, g_h);

    float* out = (float*)d_out;
    float* preds;
    float* embed;
    if (out_size == Nn + Nn * D) {
        preds = out;
        embed = out + Nn;
    } else if (out_size == Nn * D) {
        embed = out;
        cudaGetSymbolAddress((void**)&preds, g_preds_fb);
    } else {
        preds = out;
        cudaGetSymbolAddress((void**)&embed, g_embed_fb);
    }

    int sms = 148;
    cudaDeviceGetAttribute(&sms, cudaDevAttrMultiProcessorCount, 0);
    cudaFuncSetAttribute(k_gemm, cudaFuncAttributeMaxDynamicSharedMemorySize, SMEM_G);

    k_zero<<<(Nn + 255) / 256, 256>>>();
    k_degree<<<(Ee + 255) / 256, 256>>>(dst);
    k_scan1<<<NB_SCAN, 256>>>();
    k_scan2<<<1, 512>>>();
    k_scan3<<<NB_SCAN, 256>>>();
    k_fill<<<(Ee + 255) / 256, 256>>>(src, dst);

    k_agg<<<(Nn * 32 + 255) / 256, 256>>>(x);
    k_gemm<<<sms, THREADS_G, SMEM_G>>>(x, W1l, W1r, b1l, ph, nullptr,
                                       nullptr, nullptr, 1);
    k_bnstats<<<98, 256>>>();
    k_bnfin<<<1, 128>>>(gamma, beta);
    k_agg<<<(Nn * 32 + 255) / 256, 256>>>(ph);
    k_gemm<<<sms, THREADS_G, SMEM_G>>>(ph, W2l, W2r, b2l, embed, preds,
                                       fcw, fcb, 2);
}

// round 11
// speedup vs baseline: 1.3980x; 1.3980x over previous
#include <cuda_runtime.h>
#include <cstdint>

// Problem constants (fixed by the reference)
#define Nn 100000
#define Ee 600000
#define D  128
#define K2 256               // stacked K (mean | x)
#define NB_SCAN 391          // ceil(Nn/256)
#define THREADS 512
#define WARPS 16
#define NPW 5                // nodes per warp
#define WPITCH 260           // f32 pitch of W^T rows (conflict-free LDS.128)
#define SM_W (D*WPITCH)      // 33280 floats = 133120 B
#define STAGE_FLOATS (NPW*K2)
#define SMEM_BYTES ((SM_W + WARPS*STAGE_FLOATS)*4)   // 133120+81920 = 215040

// ---------------- scratch (device globals: no allocation allowed) ----------
__device__ int   g_deg[Nn];
__device__ int   g_off[Nn];
__device__ int   g_cur[Nn];
__device__ int   g_elist[Ee];
__device__ int   g_bsum[512];
__device__ __align__(16) float g_h[(size_t)Nn * D];
__device__ __align__(16) float g_bnsum[D];
__device__ __align__(16) float g_bnsq[D];
__device__ __align__(16) float g_bns[D];
__device__ __align__(16) float g_bnt[D];
__device__ float g_preds_fb[Nn];
__device__ __align__(16) float g_embed_fb[(size_t)Nn * D];

// ---------------- f32x2 packed math (Blackwell FFMA2, PTX-only path) -------
__device__ __forceinline__ unsigned long long fma2(unsigned long long a,
                                                   unsigned long long b,
                                                   unsigned long long c) {
    unsigned long long d;
    asm("fma.rn.f32x2 %0, %1, %2, %3;" : "=l"(d) : "l"(a), "l"(b), "l"(c));
    return d;
}
__device__ __forceinline__ float2 unpack2(unsigned long long v) {
    float2 r;
    asm("mov.b64 {%0, %1}, %2;" : "=f"(r.x), "=f"(r.y) : "l"(v));
    return r;
}

// ---------------- CSR build ------------------------------------------------
__global__ void k_zero() {
    int i = blockIdx.x * blockDim.x + threadIdx.x;
    if (i < Nn) g_deg[i] = 0;
    if (i < D) { g_bnsum[i] = 0.f; g_bnsq[i] = 0.f; }
}

__global__ void k_degree(const int* __restrict__ dst) {
    int e = blockIdx.x * blockDim.x + threadIdx.x;
    if (e < Ee) atomicAdd(&g_deg[dst[e]], 1);
}

__global__ void k_scan1() {
    __shared__ int s[256];
    int i = blockIdx.x * 256 + threadIdx.x;
    int v = (i < Nn) ? g_deg[i] : 0;
    s[threadIdx.x] = v; __syncthreads();
    for (int d = 128; d > 0; d >>= 1) {
        if (threadIdx.x < d) s[threadIdx.x] += s[threadIdx.x + d];
        __syncthreads();
    }
    if (threadIdx.x == 0) g_bsum[blockIdx.x] = s[0];
}

__global__ void k_scan2() {   // exclusive scan of 391 block sums, 1 block
    __shared__ int s[512];
    int t = threadIdx.x;
    int v = (t < NB_SCAN) ? g_bsum[t] : 0;
    s[t] = v; __syncthreads();
    for (int d = 1; d < 512; d <<= 1) {
        int x = (t >= d) ? s[t - d] : 0;
        __syncthreads();
        s[t] += x;
        __syncthreads();
    }
    if (t < NB_SCAN) g_bsum[t] = s[t] - v;   // exclusive
}

__global__ void k_scan3() {
    __shared__ int s[256];
    int t = threadIdx.x;
    int i = blockIdx.x * 256 + t;
    int v = (i < Nn) ? g_deg[i] : 0;
    s[t] = v; __syncthreads();
    for (int d = 1; d < 256; d <<= 1) {
        int x = (t >= d) ? s[t - d] : 0;
        __syncthreads();
        s[t] += x;
        __syncthreads();
    }
    if (i < Nn) {
        int off = g_bsum[blockIdx.x] + s[t] - v;
        g_off[i] = off;
        g_cur[i] = off;
    }
}

__global__ void k_fill(const int* __restrict__ src, const int* __restrict__ dst) {
    int e = blockIdx.x * blockDim.x + threadIdx.x;
    if (e < Ee) {
        int p = atomicAdd(&g_cur[dst[e]], 1);
        g_elist[p] = src[e];
    }
}

// ---------------- BN finalize ----------------------------------------------
__global__ void k_bnfin(const float* __restrict__ gamma,
                        const float* __restrict__ beta) {
    int j = threadIdx.x;
    if (j < D) {
        float mu  = g_bnsum[j] / (float)Nn;
        float var = g_bnsq[j] / (float)Nn - mu * mu;
        float s   = gamma[j] * rsqrtf(var + 1e-5f);
        g_bns[j] = s;
        g_bnt[j] = beta[j] - mu * s;
    }
}

// ---------------- fused SAGE layer (agg + stacked GEMM + L2norm) -----------
// A-row per node = [mean(0..127) | x(128..255)].
// Weights stored TRANSPOSED in smem: sW[j][k] = Wstack[k][j], pitch 260 f32.
// Thread owns output columns {lane, lane+32, lane+64, lane+96}; accumulators
// are f32x2 {even-k partial, odd-k partial}; A pairs come straight from
// LDS.128 (no packing MOVs).
__global__ __launch_bounds__(THREADS, 1)
void k_layer(const float* __restrict__ xin,
             const float* __restrict__ Wl, const float* __restrict__ bl,
             const float* __restrict__ Wr,
             float* __restrict__ hout, float* __restrict__ preds,
             const float* __restrict__ fcw, const float* __restrict__ fcb,
             int layer) {
    extern __shared__ float smem[];
    float* sW = smem;                  // W^T: 128 rows x 260 pitch
    float* sStage = smem + SM_W;

    int tid = threadIdx.x, warp = tid >> 5, lane = tid & 31;

    // ---- stage W transposed: Wstack[k][j] -> sW[j*260 + k] -----------------
    for (int idx = tid; idx < K2 * D; idx += THREADS) {
        int k = idx >> 7, j = idx & 127;         // lane-consecutive j: coalesced LDG
        float v = (k < D) ? __ldg(&Wl[(size_t)k * D + j])
                          : __ldg(&Wr[(size_t)(k - D) * D + j]);
        sW[j * WPITCH + k] = v;
    }

    // per-thread constants for its 4 columns {lane+32c}
    float biasc[4];
    #pragma unroll
    for (int c = 0; c < 4; c++) biasc[c] = __ldg(&bl[lane + 32 * c]);
    float4 bns4 = make_float4(0, 0, 0, 0), bnt4 = make_float4(0, 0, 0, 0);
    if (layer == 2) {
        bns4 = __ldg((const float4*)g_bns + lane);
        bnt4 = __ldg((const float4*)g_bnt + lane);
    }
    float fcwA = 0.f, fcwB = 0.f, fcb0 = 0.f;
    if (layer == 2) {
        fcwA = __ldg(&fcw[lane]);
        fcwB = __ldg(&fcw[lane + 32]);
        fcb0 = __ldg(fcb);
    }
    __syncthreads();

    float lsum[4] = {0, 0, 0, 0}, lsq[4] = {0, 0, 0, 0};

    float* A = sStage + warp * STAGE_FLOATS;     // NPW rows of 256 floats
    // per-thread W row pointers (float4 granularity)
    const float4* w4[4];
    #pragma unroll
    for (int c = 0; c < 4; c++)
        w4[c] = (const float4*)sW + (size_t)(lane + 32 * c) * (WPITCH / 4);

    const float4* xi4 = (const float4*)xin;
    const int ngroups = (Nn + NPW - 1) / NPW;

    for (int g = blockIdx.x * WARPS + warp; g < ngroups; g += gridDim.x * WARPS) {
        int base = g * NPW;
        __syncwarp();
        // ---- stage: mean-aggregate + root row (per node, per-lane float4) --
        #pragma unroll
        for (int m = 0; m < NPW; m++) {
            int node = base + m;
            float4 mean = make_float4(0, 0, 0, 0);
            float4 xr   = make_float4(0, 0, 0, 0);
            if (node < Nn) {
                int off = g_off[node];
                int dg  = g_deg[node];
                float4 a0 = make_float4(0, 0, 0, 0), a1 = make_float4(0, 0, 0, 0);
                int e = 0;
                for (; e + 1 < dg; e += 2) {
                    int s0 = __ldg(&g_elist[off + e]);
                    int s1 = __ldg(&g_elist[off + e + 1]);
                    float4 v0 = __ldg(&xi4[(size_t)s0 * 32 + lane]);
                    float4 v1 = __ldg(&xi4[(size_t)s1 * 32 + lane]);
                    a0.x += v0.x; a0.y += v0.y; a0.z += v0.z; a0.w += v0.w;
                    a1.x += v1.x; a1.y += v1.y; a1.z += v1.z; a1.w += v1.w;
                }
                if (e < dg) {
                    int s0 = __ldg(&g_elist[off + e]);
                    float4 v0 = __ldg(&xi4[(size_t)s0 * 32 + lane]);
                    a0.x += v0.x; a0.y += v0.y; a0.z += v0.z; a0.w += v0.w;
                }
                float inv = 1.f / (float)max(dg, 1);
                mean.x = (a0.x + a1.x) * inv;
                mean.y = (a0.y + a1.y) * inv;
                mean.z = (a0.z + a1.z) * inv;
                mean.w = (a0.w + a1.w) * inv;
                xr = __ldg(&xi4[(size_t)node * 32 + lane]);
                if (layer == 2) {
                    if (dg > 0) {
                        mean.x = mean.x * bns4.x + bnt4.x;
                        mean.y = mean.y * bns4.y + bnt4.y;
                        mean.z = mean.z * bns4.z + bnt4.z;
                        mean.w = mean.w * bns4.w + bnt4.w;
                    } else {
                        mean = make_float4(0, 0, 0, 0);
                    }
                    xr.x = xr.x * bns4.x + bnt4.x;
                    xr.y = xr.y * bns4.y + bnt4.y;
                    xr.z = xr.z * bns4.z + bnt4.z;
                    xr.w = xr.w * bns4.w + bnt4.w;
                }
            }
            ((float4*)(A + m * K2))[lane] = mean;          // cols 0..127
            ((float4*)(A + m * K2 + D))[lane] = xr;        // cols 128..255
        }
        __syncwarp();

        // ---- GEMM: acc[m][c] = f32x2 {even-k, odd-k} partial sums ----------
        unsigned long long acc[NPW][4];
        #pragma unroll
        for (int m = 0; m < NPW; m++)
            #pragma unroll
            for (int c = 0; c < 4; c++) acc[m][c] = 0ull;

        const float4* A4[NPW];
        #pragma unroll
        for (int m = 0; m < NPW; m++) A4[m] = (const float4*)(A + m * K2);

        #pragma unroll 2
        for (int kq = 0; kq < K2 / 4; kq++) {    // k4 = 4*kq
            // W frags: one LDS.128 per column (conflict-free)
            float4 wv0 = w4[0][kq];
            float4 wv1 = w4[1][kq];
            float4 wv2 = w4[2][kq];
            float4 wv3 = w4[3][kq];
            ulonglong2 wp0 = *reinterpret_cast<const ulonglong2*>(&wv0);
            ulonglong2 wp1 = *reinterpret_cast<const ulonglong2*>(&wv1);
            ulonglong2 wp2 = *reinterpret_cast<const ulonglong2*>(&wv2);
            ulonglong2 wp3 = *reinterpret_cast<const ulonglong2*>(&wv3);
            #pragma unroll
            for (int m = 0; m < NPW; m++) {
                float4 av = A4[m][kq];           // broadcast LDS.128
                ulonglong2 ap = *reinterpret_cast<const ulonglong2*>(&av);
                acc[m][0] = fma2(ap.x, wp0.x, acc[m][0]);
                acc[m][1] = fma2(ap.x, wp1.x, acc[m][1]);
                acc[m][2] = fma2(ap.x, wp2.x, acc[m][2]);
                acc[m][3] = fma2(ap.x, wp3.x, acc[m][3]);
                acc[m][0] = fma2(ap.y, wp0.y, acc[m][0]);
                acc[m][1] = fma2(ap.y, wp1.y, acc[m][1]);
                acc[m][2] = fma2(ap.y, wp2.y, acc[m][2]);
                acc[m][3] = fma2(ap.y, wp3.y, acc[m][3]);
            }
        }

        // ---- epilogue per node: horizontal add, bias, L2-norm, extras ------
        #pragma unroll
        for (int m = 0; m < NPW; m++) {
            int node = base + m;
            if (node >= Nn) continue;            // uniform across warp
            float o[4];
            float ss = 0.f;
            #pragma unroll
            for (int c = 0; c < 4; c++) {
                float2 pr = unpack2(acc[m][c]);
                float v = pr.x + pr.y + biasc[c];
                o[c] = v;
                ss += v * v;
            }
            #pragma unroll
            for (int t = 16; t > 0; t >>= 1) ss += __shfl_xor_sync(0xffffffffu, ss, t);
            float inv = 1.f / fmaxf(sqrtf(ss), 1e-12f);
            float* hp = hout + (size_t)node * D + lane;
            if (layer == 1) {
                #pragma unroll
                for (int c = 0; c < 4; c++) {
                    float v = fmaxf(o[c] * inv, 0.f);
                    o[c] = v;
                    lsum[c] += v; lsq[c] += v * v;
                    hp[32 * c] = v;
                }
            } else {
                #pragma unroll
                for (int c = 0; c < 4; c++) {
                    o[c] *= inv;
                    hp[32 * c] = o[c];
                }
                float p = o[0] * fcwA + o[1] * fcwB;
                #pragma unroll
                for (int t = 16; t > 0; t >>= 1) p += __shfl_xor_sync(0xffffffffu, p, t);
                if (lane == 0) preds[node] = p + fcb0;
            }
        }
    }

    // ---- BN stats: block-reduce in smem, then 128 global atomics -----------
    if (layer == 1) {
        __syncthreads();
        float* bs  = smem;          // reuse sW region (GEMM done)
        float* bss = smem + 128;
        if (tid < 256) bs[tid] = 0.f;
        __syncthreads();
        #pragma unroll
        for (int c = 0; c < 4; c++) {
            atomicAdd(&bs[lane + 32 * c], lsum[c]);
            atomicAdd(&bss[lane + 32 * c], lsq[c]);
        }
        __syncthreads();
        if (tid < 128) {
            atomicAdd(&g_bnsum[tid], bs[tid]);
            atomicAdd(&g_bnsq[tid], bss[tid]);
        }
    }
}

// ---------------- launch ----------------------------------------------------
extern "C" void kernel_launch(void* const* d_in, const int* in_sizes, int n_in,
                              void* d_out, int out_size) {
    const float* x     = (const float*)d_in[0];
    const int*   ei    = (const int*)d_in[1];
    const int*   src   = ei;
    const int*   dst   = ei + Ee;
    const float* W1l   = (const float*)d_in[2];
    const float* b1l   = (const float*)d_in[3];
    const float* W1r   = (const float*)d_in[4];
    const float* gamma = (const float*)d_in[5];
    const float* beta  = (const float*)d_in[6];
    const float* W2l   = (const float*)d_in[7];
    const float* b2l   = (const float*)d_in[8];
    const float* W2r   = (const float*)d_in[9];
    const float* fcw   = (const float*)d_in[10];
    const float* fcb   = (const float*)d_in[11];

    float* ph = nullptr;
    cudaGetSymbolAddress((void**)&ph, g_h);

    float* out = (float*)d_out;
    float* preds;
    float* embed;
    if (out_size == Nn + Nn * D) {            // (preds, embed) concatenated
        preds = out;
        embed = out + Nn;
    } else if (out_size == Nn * D) {          // embed only
        embed = out;
        cudaGetSymbolAddress((void**)&preds, g_preds_fb);
    } else {                                   // preds only (or unknown)
        preds = out;
        cudaGetSymbolAddress((void**)&embed, g_embed_fb);
    }

    int sms = 148;
    cudaDeviceGetAttribute(&sms, cudaDevAttrMultiProcessorCount, 0);

    cudaFuncSetAttribute(k_layer, cudaFuncAttributeMaxDynamicSharedMemorySize,
                         SMEM_BYTES);

    k_zero<<<(Nn + 255) / 256, 256>>>();
    k_degree<<<(Ee + 255) / 256, 256>>>(dst);
    k_scan1<<<NB_SCAN, 256>>>();
    k_scan2<<<1, 512>>>();
    k_scan3<<<NB_SCAN, 256>>>();
    k_fill<<<(Ee + 255) / 256, 256>>>(src, dst);
    k_layer<<<sms, THREADS, SMEM_BYTES>>>(x, W1l, b1l, W1r, ph,
                                          nullptr, nullptr, nullptr, 1);
    k_bnfin<<<1, 128>>>(gamma, beta);
    k_layer<<<sms, THREADS, SMEM_BYTES>>>(ph, W2l, b2l, W2r, embed,
                                          preds, fcw, fcb, 2);
}

// round 12
// speedup vs baseline: 1.6671x; 1.1925x over previous
#include <cuda_runtime.h>
#include <cstdint>

// Problem constants (fixed by the reference)
#define Nn 100000
#define Ee 600000
#define D  128
#define K2 256               // stacked K (mean | x)
#define NB_SCAN 391          // ceil(Nn/256)
#define THREADS 512
#define WARPS 16
#define NPW 6                // nodes per warp
#define SM_W (K2*D)          // floats of stacked weights [Wl;Wr]
#define STAGE_FLOATS (NPW*K2)
#define SMEM_BYTES ((SM_W + WARPS*STAGE_FLOATS)*4)   // 131072+98304 = 229376

// ---------------- scratch (device globals: no allocation allowed) ----------
__device__ int   g_deg[Nn];
__device__ int   g_off[Nn];
__device__ int   g_cur[Nn];
__device__ int   g_elist[Ee];
__device__ int   g_bsum[512];
__device__ __align__(16) float g_h[(size_t)Nn * D];
__device__ __align__(16) float g_mean[(size_t)Nn * D];
__device__ __align__(16) float g_bnsum[D];
__device__ __align__(16) float g_bnsq[D];
__device__ __align__(16) float g_bns[D];
__device__ __align__(16) float g_bnt[D];
__device__ float g_preds_fb[Nn];
__device__ __align__(16) float g_embed_fb[(size_t)Nn * D];

// ---------------- f32x2 packed math (Blackwell FFMA2, PTX-only path) -------
__device__ __forceinline__ unsigned long long fma2(unsigned long long a,
                                                   unsigned long long b,
                                                   unsigned long long c) {
    unsigned long long d;
    asm("fma.rn.f32x2 %0, %1, %2, %3;" : "=l"(d) : "l"(a), "l"(b), "l"(c));
    return d;
}
__device__ __forceinline__ unsigned long long pack2(float a) {
    unsigned long long d;
    asm("mov.b64 %0, {%1, %1};" : "=l"(d) : "f"(a));
    return d;
}
__device__ __forceinline__ float2 unpack2(unsigned long long v) {
    float2 r;
    asm("mov.b64 {%0, %1}, %2;" : "=f"(r.x), "=f"(r.y) : "l"(v));
    return r;
}

// ---------------- CSR build ------------------------------------------------
__global__ void k_zero() {
    int i = blockIdx.x * blockDim.x + threadIdx.x;
    if (i < Nn) g_deg[i] = 0;
    if (i < D) { g_bnsum[i] = 0.f; g_bnsq[i] = 0.f; }
}

__global__ void k_degree(const int* __restrict__ dst) {
    int e = blockIdx.x * blockDim.x + threadIdx.x;
    if (e < Ee) atomicAdd(&g_deg[dst[e]], 1);
}

__global__ void k_scan1() {
    __shared__ int s[256];
    int i = blockIdx.x * 256 + threadIdx.x;
    int v = (i < Nn) ? g_deg[i] : 0;
    s[threadIdx.x] = v; __syncthreads();
    for (int d = 128; d > 0; d >>= 1) {
        if (threadIdx.x < d) s[threadIdx.x] += s[threadIdx.x + d];
        __syncthreads();
    }
    if (threadIdx.x == 0) g_bsum[blockIdx.x] = s[0];
}

__global__ void k_scan2() {   // exclusive scan of 391 block sums, 1 block
    __shared__ int s[512];
    int t = threadIdx.x;
    int v = (t < NB_SCAN) ? g_bsum[t] : 0;
    s[t] = v; __syncthreads();
    for (int d = 1; d < 512; d <<= 1) {
        int x = (t >= d) ? s[t - d] : 0;
        __syncthreads();
        s[t] += x;
        __syncthreads();
    }
    if (t < NB_SCAN) g_bsum[t] = s[t] - v;   // exclusive
}

__global__ void k_scan3() {
    __shared__ int s[256];
    int t = threadIdx.x;
    int i = blockIdx.x * 256 + t;
    int v = (i < Nn) ? g_deg[i] : 0;
    s[t] = v; __syncthreads();
    for (int d = 1; d < 256; d <<= 1) {
        int x = (t >= d) ? s[t - d] : 0;
        __syncthreads();
        s[t] += x;
        __syncthreads();
    }
    if (i < Nn) {
        int off = g_bsum[blockIdx.x] + s[t] - v;
        g_off[i] = off;
        g_cur[i] = off;
    }
}

__global__ void k_fill(const int* __restrict__ src, const int* __restrict__ dst) {
    int e = blockIdx.x * blockDim.x + threadIdx.x;
    if (e < Ee) {
        int p = atomicAdd(&g_cur[dst[e]], 1);
        g_elist[p] = src[e];
    }
}

// ---------------- mean aggregation (warp per node, latency-hidden) ---------
__global__ __launch_bounds__(256)
void k_agg(const float* __restrict__ xin) {
    int w = (blockIdx.x * blockDim.x + threadIdx.x) >> 5;
    int lane = threadIdx.x & 31;
    if (w >= Nn) return;
    int off = g_off[w], dg = g_deg[w];
    const float4* xi4 = (const float4*)xin;
    float4 a0 = make_float4(0, 0, 0, 0), a1 = make_float4(0, 0, 0, 0);
    int e = 0;
    for (; e + 1 < dg; e += 2) {
        int s0 = __ldg(&g_elist[off + e]);
        int s1 = __ldg(&g_elist[off + e + 1]);
        float4 v0 = __ldg(&xi4[(size_t)s0 * 32 + lane]);
        float4 v1 = __ldg(&xi4[(size_t)s1 * 32 + lane]);
        a0.x += v0.x; a0.y += v0.y; a0.z += v0.z; a0.w += v0.w;
        a1.x += v1.x; a1.y += v1.y; a1.z += v1.z; a1.w += v1.w;
    }
    if (e < dg) {
        int s0 = __ldg(&g_elist[off + e]);
        float4 v0 = __ldg(&xi4[(size_t)s0 * 32 + lane]);
        a0.x += v0.x; a0.y += v0.y; a0.z += v0.z; a0.w += v0.w;
    }
    float inv = 1.f / (float)max(dg, 1);
    float4 m = make_float4((a0.x + a1.x) * inv, (a0.y + a1.y) * inv,
                           (a0.z + a1.z) * inv, (a0.w + a1.w) * inv);
    ((float4*)g_mean)[(size_t)w * 32 + lane] = m;
}

// ---------------- BN finalize ----------------------------------------------
__global__ void k_bnfin(const float* __restrict__ gamma,
                        const float* __restrict__ beta) {
    int j = threadIdx.x;
    if (j < D) {
        float mu  = g_bnsum[j] / (float)Nn;
        float var = g_bnsq[j] / (float)Nn - mu * mu;
        float s   = gamma[j] * rsqrtf(var + 1e-5f);
        g_bns[j] = s;
        g_bnt[j] = beta[j] - mu * s;
    }
}

// ---------------- fused SAGE layer (stacked GEMM + L2norm) -----------------
// A-row per node = [mean(0..127) | x(128..255)], weights stacked [Wl;Wr].
// Mean comes precomputed from g_mean (coalesced read, no gather here).
// layer==1: xin = x, writes hout = relu(normalize(out)), accumulates BN stats
// layer==2: xin = g_h, folds BN affine into mean & root term, writes
//           embed + preds
__global__ __launch_bounds__(THREADS, 1)
void k_layer(const float* __restrict__ xin,
             const float* __restrict__ Wl, const float* __restrict__ bl,
             const float* __restrict__ Wr,
             float* __restrict__ hout, float* __restrict__ preds,
             const float* __restrict__ fcw, const float* __restrict__ fcb,
             int layer) {
    extern __shared__ float smem[];
    float* sW = smem;                  // [256][128] stacked
    float* sStage = smem + SM_W;

    int tid = threadIdx.x, warp = tid >> 5, lane = tid & 31;

    // Load stacked weight matrix into shared memory (float4 copies)
    {
        const float4* a = (const float4*)Wl;
        const float4* b = (const float4*)Wr;
        float4* dw = (float4*)sW;
        for (int i = tid; i < (D * D) / 4; i += THREADS) {
            dw[i] = a[i];
            dw[(D * D) / 4 + i] = b[i];
        }
    }
    float4 bias = ((const float4*)bl)[lane];
    float4 bns = make_float4(0, 0, 0, 0), bnt = make_float4(0, 0, 0, 0);
    if (layer == 2) {
        bns = ((const float4*)g_bns)[lane];
        bnt = ((const float4*)g_bnt)[lane];
    }
    __syncthreads();

    float lsum[4] = {0, 0, 0, 0}, lsq[4] = {0, 0, 0, 0};

    float* A = sStage + warp * STAGE_FLOATS;   // NPW rows of 256 floats

    const float4* xi4 = (const float4*)xin;
    const float4* mn4 = (const float4*)g_mean;
    const int ngroups = (Nn + NPW - 1) / NPW;

    for (int g = blockIdx.x * WARPS + warp; g < ngroups; g += gridDim.x * WARPS) {
        int base = g * NPW;
        __syncwarp();
        // ---- stage: coalesced mean + root row (per node, per-lane float4) --
        #pragma unroll
        for (int m = 0; m < NPW; m++) {
            int node = base + m;
            float4 mean = make_float4(0, 0, 0, 0);
            float4 xr   = make_float4(0, 0, 0, 0);
            if (node < Nn) {
                mean = __ldg(&mn4[(size_t)node * 32 + lane]);
                xr   = __ldg(&xi4[(size_t)node * 32 + lane]);
                if (layer == 2) {
                    // fold BN affine; mean over 0 neighbors stays 0
                    if (__ldg(&g_deg[node]) > 0) {
                        mean.x = mean.x * bns.x + bnt.x;
                        mean.y = mean.y * bns.y + bnt.y;
                        mean.z = mean.z * bns.z + bnt.z;
                        mean.w = mean.w * bns.w + bnt.w;
                    } else {
                        mean = make_float4(0, 0, 0, 0);
                    }
                    xr.x = xr.x * bns.x + bnt.x;
                    xr.y = xr.y * bns.y + bnt.y;
                    xr.z = xr.z * bns.z + bnt.z;
                    xr.w = xr.w * bns.w + bnt.w;
                }
            }
            ((float4*)(A + m * K2))[lane] = mean;          // cols 0..127
            ((float4*)(A + m * K2 + D))[lane] = xr;        // cols 128..255
        }
        __syncwarp();

        // ---- stacked GEMM: out = A[256] @ sW[256][128], f32x2 accumulators -
        unsigned long long accA[NPW], accB[NPW];
        #pragma unroll
        for (int m = 0; m < NPW; m++) { accA[m] = 0ull; accB[m] = 0ull; }

        const ulonglong2* wv = (const ulonglong2*)sW;   // 32 ulonglong2 per row
        #pragma unroll 2
        for (int k4 = 0; k4 < K2; k4 += 4) {
            ulonglong2 w0 = wv[(k4 + 0) * 32 + lane];   // W[k][4lane..4lane+3]
            ulonglong2 w1 = wv[(k4 + 1) * 32 + lane];
            ulonglong2 w2 = wv[(k4 + 2) * 32 + lane];
            ulonglong2 w3 = wv[(k4 + 3) * 32 + lane];
            #pragma unroll
            for (int m = 0; m < NPW; m++) {
                float4 a = *(const float4*)(A + m * K2 + k4);  // broadcast
                unsigned long long p0 = pack2(a.x);
                unsigned long long p1 = pack2(a.y);
                unsigned long long p2 = pack2(a.z);
                unsigned long long p3 = pack2(a.w);
                accA[m] = fma2(p0, w0.x, accA[m]); accB[m] = fma2(p0, w0.y, accB[m]);
                accA[m] = fma2(p1, w1.x, accA[m]); accB[m] = fma2(p1, w1.y, accB[m]);
                accA[m] = fma2(p2, w2.x, accA[m]); accB[m] = fma2(p2, w2.y, accB[m]);
                accA[m] = fma2(p3, w3.x, accA[m]); accB[m] = fma2(p3, w3.y, accB[m]);
            }
        }

        // ---- epilogue per node: bias, L2-normalize, layer-specific ---------
        #pragma unroll
        for (int m = 0; m < NPW; m++) {
            int node = base + m;
            if (node >= Nn) continue;   // uniform across warp
            float2 p0 = unpack2(accA[m]);
            float2 p1 = unpack2(accB[m]);
            float o0 = p0.x + bias.x;
            float o1 = p0.y + bias.y;
            float o2 = p1.x + bias.z;
            float o3 = p1.y + bias.w;
            float ss = o0 * o0 + o1 * o1 + o2 * o2 + o3 * o3;
            #pragma unroll
            for (int t = 16; t > 0; t >>= 1) ss += __shfl_xor_sync(0xffffffffu, ss, t);
            float inv = 1.f / fmaxf(sqrtf(ss), 1e-12f);
            o0 *= inv; o1 *= inv; o2 *= inv; o3 *= inv;
            if (layer == 1) {
                o0 = fmaxf(o0, 0.f); o1 = fmaxf(o1, 0.f);
                o2 = fmaxf(o2, 0.f); o3 = fmaxf(o3, 0.f);
                lsum[0] += o0; lsq[0] += o0 * o0;
                lsum[1] += o1; lsq[1] += o1 * o1;
                lsum[2] += o2; lsq[2] += o2 * o2;
                lsum[3] += o3; lsq[3] += o3 * o3;
                ((float4*)hout)[(size_t)node * 32 + lane] = make_float4(o0, o1, o2, o3);
            } else {
                ((float4*)hout)[(size_t)node * 32 + lane] = make_float4(o0, o1, o2, o3);
                float p = 0.f;
                if (lane < 16) {
                    int j = 4 * lane;
                    p = o0 * fcw[j] + o1 * fcw[j + 1] + o2 * fcw[j + 2] + o3 * fcw[j + 3];
                }
                #pragma unroll
                for (int t = 8; t > 0; t >>= 1) p += __shfl_down_sync(0xffffffffu, p, t);
                if (lane == 0) preds[node] = p + fcb[0];
            }
        }
    }

    // ---- BN stats: block-reduce then 128 global atomics per block ----------
    if (layer == 1) {
        __syncthreads();
        float* bs  = smem;
        float* bss = smem + 128;
        if (tid < 256) { bs[tid] = 0.f; }
        __syncthreads();
        #pragma unroll
        for (int i = 0; i < 4; i++) {
            atomicAdd(&bs[4 * lane + i], lsum[i]);
            atomicAdd(&bss[4 * lane + i], lsq[i]);
        }
        __syncthreads();
        if (tid < 128) {
            atomicAdd(&g_bnsum[tid], bs[tid]);
            atomicAdd(&g_bnsq[tid], bss[tid]);
        }
    }
}

// ---------------- launch ----------------------------------------------------
extern "C" void kernel_launch(void* const* d_in, const int* in_sizes, int n_in,
                              void* d_out, int out_size) {
    const float* x     = (const float*)d_in[0];
    const int*   ei    = (const int*)d_in[1];
    const int*   src   = ei;
    const int*   dst   = ei + Ee;
    const float* W1l   = (const float*)d_in[2];
    const float* b1l   = (const float*)d_in[3];
    const float* W1r   = (const float*)d_in[4];
    const float* gamma = (const float*)d_in[5];
    const float* beta  = (const float*)d_in[6];
    const float* W2l   = (const float*)d_in[7];
    const float* b2l   = (const float*)d_in[8];
    const float* W2r   = (const float*)d_in[9];
    const float* fcw   = (const float*)d_in[10];
    const float* fcb   = (const float*)d_in[11];

    float* ph = nullptr;
    cudaGetSymbolAddress((void**)&ph, g_h);

    float* out = (float*)d_out;
    float* preds;
    float* embed;
    if (out_size == Nn + Nn * D) {            // (preds, embed) concatenated
        preds = out;
        embed = out + Nn;
    } else if (out_size == Nn * D) {          // embed only
        embed = out;
        cudaGetSymbolAddress((void**)&preds, g_preds_fb);
    } else {                                   // preds only (or unknown)
        preds = out;
        cudaGetSymbolAddress((void**)&embed, g_embed_fb);
    }

    int sms = 148;
    cudaDeviceGetAttribute(&sms, cudaDevAttrMultiProcessorCount, 0);

    cudaFuncSetAttribute(k_layer, cudaFuncAttributeMaxDynamicSharedMemorySize,
                         SMEM_BYTES);

    k_zero<<<(Nn + 255) / 256, 256>>>();
    k_degree<<<(Ee + 255) / 256, 256>>>(dst);
    k_scan1<<<NB_SCAN, 256>>>();
    k_scan2<<<1, 512>>>();
    k_scan3<<<NB_SCAN, 256>>>();
    k_fill<<<(Ee + 255) / 256, 256>>>(src, dst);

    k_agg<<<(Nn * 32 + 255) / 256, 256>>>(x);
    k_layer<<<sms, THREADS, SMEM_BYTES>>>(x, W1l, b1l, W1r, ph,
                                          nullptr, nullptr, nullptr, 1);
    k_bnfin<<<1, 128>>>(gamma, beta);
    k_agg<<<(Nn * 32 + 255) / 256, 256>>>(ph);
    k_layer<<<sms, THREADS, SMEM_BYTES>>>(ph, W2l, b2l, W2r, embed,
                                          preds, fcw, fcb, 2);
}